// round 4
// baseline (speedup 1.0000x reference)
#include <cuda_runtime.h>
#include <cstdint>

// MultiDirectionPattern: masked 8-direction pooling + saliency gather.
// Persistent double-buffered pipeline: 608 CTAs (4/SM), each loops over work
// items (feat tiles of 128 rows, or one batch of the saliency gather),
// prefetching item k+1 with cp.async while computing item k.

static constexpr int HW   = 49;    // 7*7
static constexpr int TPB  = 128;
static constexpr int SROW = 3136;  // 56*56
static constexpr int BUF_FLOATS = 6400;                 // one pipeline buffer
static constexpr int SM_FLOATS  = 2 * BUF_FLOATS + 392; // + mask
static constexpr int SM_BYTES   = SM_FLOATS * 4;        // 52768 B -> 4 CTAs/SM
static constexpr int GRID_PERSIST = 608;                // 152 SMs * 4

// Expected nonzero cells per direction (incl. center 24), 10 each.
__constant__ unsigned char c_idx[80] = {
    24,25,26,27,32,33,34,40,41,48,
    24,31,32,38,39,40,45,46,47,48,
    24,30,31,36,37,38,42,43,44,45,
    21,22,23,24,28,29,30,35,36,42,
     0, 7, 8,14,15,16,21,22,23,24,
     0, 1, 2, 3, 8, 9,10,16,17,24,
     3, 4, 5, 6,10,11,12,17,18,24,
     6,12,13,18,19,20,24,25,26,27
};

__device__ __forceinline__ void cp16(uint32_t dst, const void* src) {
    asm volatile("cp.async.cg.shared.global [%0], [%1], 16;\n" :: "r"(dst), "l"(src));
}
__device__ __forceinline__ void cp4(uint32_t dst, const void* src) {
    asm volatile("cp.async.ca.shared.global [%0], [%1], 4;\n" :: "r"(dst), "l"(src));
}
__device__ __forceinline__ void cp_commit() {
    asm volatile("cp.async.commit_group;\n" ::: "memory");
}
template <int NG>
__device__ __forceinline__ void cp_wait() {
    asm volatile("cp.async.wait_group %0;\n" :: "n"(NG) : "memory");
}

__global__ __launch_bounds__(TPB) void fused_kernel(
    const float* __restrict__ x,
    const float* __restrict__ s,
    const float* __restrict__ fm,
    const int*   __restrict__ sal_idx,
    float*       __restrict__ out,
    int rows,             // B*C
    int nfb,              // feat tiles (items [0, nfb))
    int B,                // batch (items [nfb, nfb+B))
    int N,                // saliency points per direction
    long long feat_elems  // rows*8
) {
    extern __shared__ __align__(16) float sm[];
    const int t = threadIdx.x;
    const int g = blockIdx.x;
    const int G = gridDim.x;
    const uint32_t sb0 = (uint32_t)__cvta_generic_to_shared(sm);
    float* sm_fm = sm + 2 * BUF_FLOATS;

    const int nitems = nfb + B;
    const int M = 8 * N;
    const bool stage_idx = (SROW + M) <= BUF_FLOATS;
    int my = (g < nitems) ? (nitems - g + G - 1) / G : 0;

    // ---- issue helper: stage item (g + k*G) into buffer bf ----
    auto issue = [&](int k, int bf) {
        const int it = g + k * G;
        const uint32_t dst = sb0 + (uint32_t)bf * (BUF_FLOATS * 4);
        if (it < nfb) {
            const long long row0 = (long long)it * TPB;
            int rh = rows - (int)row0;
            if (rh > TPB) rh = TPB;
            const float* xb = x + row0 * HW;        // 16B aligned
            const int total = rh * HW;
            const int n4 = total >> 2;
            const float4* xb4 = (const float4*)xb;
            for (int i = t; i < n4; i += TPB) cp16(dst + i * 16, xb4 + i);
            for (int i = 4 * n4 + t; i < total; i += TPB) cp4(dst + i * 4, xb + i);
        } else {
            const int b = it - nfb;
            const float4* sb4 = (const float4*)(s + (long long)b * SROW); // 16B aligned
            for (int i = t; i < SROW / 4; i += TPB) cp16(dst + i * 16, sb4 + i);
            if (stage_idx) {
                const int4* si4 = (const int4*)sal_idx;
                const int m4 = M >> 2;
                for (int i = t; i < m4; i += TPB)
                    cp16(dst + SROW * 4 + i * 16, si4 + i);
                for (int i = 4 * m4 + t; i < M; i += TPB)
                    cp4(dst + SROW * 4 + i * 4, sal_idx + i);
            }
        }
    };

    // ---- prologue: prefetch first item, then load+verify mask (overlapped) ----
    if (my > 0) issue(0, 0);
    cp_commit();

    __shared__ unsigned long long mb[8];
    __shared__ int bad;
    __shared__ float invc[8];
    if (t == 0) bad = 0;
    if (t < 8) {
        unsigned long long m = 0;
        #pragma unroll
        for (int j = 0; j < 10; ++j) m |= 1ULL << c_idx[t * 10 + j];
        mb[t] = m;
    }
    for (int i = t; i < 392; i += TPB) sm_fm[i] = fm[i];
    __syncthreads();
    {
        int mybad = 0;
        #pragma unroll
        for (int j = 0; j < 4; ++j) {
            int i = t + j * TPB;
            if (i < 392) {
                int p = i / HW, k = i - p * HW;
                float e = ((mb[p] >> k) & 1ULL) ? 1.0f : 0.0f;
                if (sm_fm[i] != e) mybad = 1;
            }
        }
        if (mybad) atomicOr(&bad, 1);
    }
    __syncthreads();
    const bool fb = (bad != 0);
    if (fb) {
        // build scaled transposed weights in place (rare generic path)
        if (t < 8) {
            int c = 0;
            for (int k = 0; k < HW; ++k) c += (sm_fm[t * HW + k] != 0.0f) ? 1 : 0;
            invc[t] = 1.0f / (float)c;
        }
        __syncthreads();
        float v[4]; int ii[4];
        #pragma unroll
        for (int j = 0; j < 4; ++j) {
            int i = t + j * TPB;
            ii[j] = -1;
            if (i < 392) {
                int p = i / HW, k = i - p * HW;
                v[j] = sm_fm[i] * invc[p];
                ii[j] = k * 8 + p;
            }
        }
        __syncthreads();
        #pragma unroll
        for (int j = 0; j < 4; ++j) if (ii[j] >= 0) sm_fm[ii[j]] = v[j];
        // visibility of rebuilt weights covered by the loop's barriers
    }

    // ---- main pipeline ----
    for (int k = 0; k < my; ++k) {
        __syncthreads();                 // prev compute done before reusing its buffer
        if (k + 1 < my) {
            issue(k + 1, (k + 1) & 1);
            cp_commit();
            cp_wait<1>();                // group k complete
        } else {
            cp_wait<0>();
        }
        __syncthreads();                 // tile k visible to all threads

        const int it = g + k * G;
        float* bufp = sm + (k & 1) * BUF_FLOATS;

        if (it < nfb) {
            // ---------- feat tile: 128 rows x 49 ----------
            const long long row0 = (long long)it * TPB;
            int rh = rows - (int)row0;
            if (rh > TPB) rh = TPB;
            if (t < rh) {
                const float* xr = bufp + t * HW;  // stride 49: conflict-free LDS
                float o[8];
                if (!fb) {
                    const float x24 = xr[24];
                    float R0 = xr[25] + xr[26] + xr[27];
                    float R1 = xr[32] + xr[40] + xr[48];
                    float R2 = xr[31] + xr[38] + xr[45];
                    float R3 = xr[30] + xr[36] + xr[42];
                    float R4 = xr[21] + xr[22] + xr[23];
                    float R5 = xr[ 0] + xr[ 8] + xr[16];
                    float R6 = xr[ 3] + xr[10] + xr[17];
                    float R7 = xr[ 6] + xr[12] + xr[18];
                    float I0 = xr[33] + xr[34] + xr[41];
                    float I1 = xr[39] + xr[46] + xr[47];
                    float I2 = xr[37] + xr[43] + xr[44];
                    float I3 = xr[28] + xr[29] + xr[35];
                    float I4 = xr[ 7] + xr[14] + xr[15];
                    float I5 = xr[ 1] + xr[ 2] + xr[ 9];
                    float I6 = xr[ 4] + xr[ 5] + xr[11];
                    float I7 = xr[13] + xr[19] + xr[20];
                    const float w = 0.1f;
                    o[0] = (R0 + I0 + R1 + x24) * w;
                    o[1] = (R1 + I1 + R2 + x24) * w;
                    o[2] = (R2 + I2 + R3 + x24) * w;
                    o[3] = (R3 + I3 + R4 + x24) * w;
                    o[4] = (R4 + I4 + R5 + x24) * w;
                    o[5] = (R5 + I5 + R6 + x24) * w;
                    o[6] = (R6 + I6 + R7 + x24) * w;
                    o[7] = (R7 + I7 + R0 + x24) * w;
                } else {
                    float a[8] = {0, 0, 0, 0, 0, 0, 0, 0};
                    for (int kk = 0; kk < HW; ++kk) {
                        float vv = xr[kk];
                        const float4* w4 = (const float4*)(sm_fm + kk * 8);
                        float4 m0 = w4[0], m1 = w4[1];
                        a[0] += vv * m0.x; a[1] += vv * m0.y; a[2] += vv * m0.z; a[3] += vv * m0.w;
                        a[4] += vv * m1.x; a[5] += vv * m1.y; a[6] += vv * m1.z; a[7] += vv * m1.w;
                    }
                    #pragma unroll
                    for (int p = 0; p < 8; ++p) o[p] = a[p];
                }
                float4* op = (float4*)(out + (row0 + t) * 8);
                op[0] = make_float4(o[0], o[1], o[2], o[3]);
                op[1] = make_float4(o[4], o[5], o[6], o[7]);
            }
        } else {
            // ---------- sal gather: one batch ----------
            const int b = it - nfb;
            float* ob = out + feat_elems + (long long)b * M;
            if (stage_idx) {
                const int* sm_idx = (const int*)(bufp + SROW);
                for (int q = t; q < M; q += TPB) {
                    int n = q >> 3;
                    int p = q & 7;
                    ob[q] = bufp[sm_idx[p * N + n]];
                }
            } else {
                for (int q = t; q < M; q += TPB) {
                    int n = q >> 3;
                    int p = q & 7;
                    ob[q] = bufp[sal_idx[p * N + n]];
                }
            }
        }
    }
}

extern "C" void kernel_launch(void* const* d_in, const int* in_sizes, int n_in,
                              void* d_out, int out_size) {
    const float* x       = (const float*)d_in[0];
    const float* s       = (const float*)d_in[1];
    const float* fm      = (const float*)d_in[2];
    const int*   sal_idx = (const int*)d_in[3];
    float*       out     = (float*)d_out;

    const int rows = in_sizes[0] / HW;    // B*C
    const int B    = in_sizes[1] / SROW;  // batch
    const int N    = in_sizes[3] / 8;     // points per direction
    const int nfb  = (rows + TPB - 1) / TPB;
    const long long feat_elems = (long long)rows * 8;

    static bool attr_set = false;
    if (!attr_set) {
        cudaFuncSetAttribute(fused_kernel,
                             cudaFuncAttributeMaxDynamicSharedMemorySize, SM_BYTES);
        attr_set = true;
    }

    int grid = nfb + B;
    if (grid > GRID_PERSIST) grid = GRID_PERSIST;
    fused_kernel<<<grid, TPB, SM_BYTES>>>(x, s, fm, sal_idx, out,
                                          rows, nfb, B, N, feat_elems);
}

// round 5
// speedup vs baseline: 1.1122x; 1.1122x over previous
#include <cuda_runtime.h>
#include <cstdint>

// MultiDirectionPattern: masked 8-direction pooling + saliency gather.
// One tile per CTA (R3 structure), but the feat path is WARP-AUTONOMOUS:
// each warp stages its own 32 rows with cp.async and syncs with
// wait_group+syncwarp only — no __syncthreads — so warps drift freely and
// DRAM demand stays continuous.

static constexpr int HW   = 49;    // 7*7
static constexpr int TPB  = 128;
static constexpr int SROW = 3136;  // 56*56
static constexpr int WROWS = 32;   // rows per warp
static constexpr int WF   = WROWS * HW;   // 1568 floats per warp slice
static constexpr int SM_FLOATS = 4 * WF;  // 6272 floats = 25088 B

// Expected sector bitmasks (bit k set <=> feat_mask[p][k] != 0), 10 cells each.
__constant__ unsigned long long c_mb[8] = {
    0x000103070F000000ULL,  // p0: 24,25,26,27,32,33,34,40,41,48
    0x0001E1C181000000ULL,  // p1: 24,31,32,38,39,40,45,46,47,48
    0x00003C70C1000000ULL,  // p2: 24,30,31,36,37,38,42,43,44,45
    0x0000041871E00000ULL,  // p3: 21,22,23,24,28,29,30,35,36,42
    0x0000000001E1C181ULL,  // p4: 0,7,8,14,15,16,21,22,23,24
    0x000000000103070FULL,  // p5: 0,1,2,3,8,9,10,16,17,24
    0x0000000001061C78ULL,  // p6: 3,4,5,6,10,11,12,17,18,24
    0x000000000F1C3040ULL   // p7: 6,12,13,18,19,20,24,25,26,27
};

__device__ __forceinline__ void cp16(uint32_t dst, const void* src) {
    asm volatile("cp.async.cg.shared.global [%0], [%1], 16;\n" :: "r"(dst), "l"(src));
}
__device__ __forceinline__ void cp4(uint32_t dst, const void* src) {
    asm volatile("cp.async.ca.shared.global [%0], [%1], 4;\n" :: "r"(dst), "l"(src));
}
__device__ __forceinline__ void cp_commit() {
    asm volatile("cp.async.commit_group;\n" ::: "memory");
}
__device__ __forceinline__ void cp_wait_all() {
    asm volatile("cp.async.wait_group 0;\n" ::: "memory");
}

__global__ __launch_bounds__(TPB) void fused_kernel(
    const float* __restrict__ x,
    const float* __restrict__ s,
    const float* __restrict__ fm,
    const int*   __restrict__ sal_idx,
    float*       __restrict__ out,
    int rows,             // B*C
    int B,                // batch (sal blocks are blk < B)
    int N,                // saliency points per direction
    long long feat_elems  // rows*8
) {
    __shared__ __align__(16) float sm[SM_FLOATS];
    const int blk = blockIdx.x;
    const int t   = threadIdx.x;
    const uint32_t sbase = (uint32_t)__cvta_generic_to_shared(sm);

    if (blk >= B) {
        // ============ feat tile: warp-autonomous, 32 rows/warp ============
        const int w    = t >> 5;
        const int lane = t & 31;
        const long long wrow0 = (long long)(blk - B) * TPB + (long long)w * WROWS;
        long long rem = rows - wrow0;
        if (rem <= 0) return;                    // no barriers in this path
        const int rh = rem < WROWS ? (int)rem : WROWS;

        float* wbuf = sm + w * WF;
        const uint32_t dst = sbase + (uint32_t)w * (WF * 4);
        const float* xw = x + wrow0 * HW;        // wrow0 mult of 32 -> 16B aligned
        const int total = rh * HW;
        const int n4 = total >> 2;
        const float4* xw4 = (const float4*)xw;
        for (int i = lane; i < n4; i += 32) cp16(dst + i * 16, xw4 + i);
        for (int i = 4 * n4 + lane; i < total; i += 32) cp4(dst + i * 4, xw + i);
        cp_commit();

        // verify mask while the copy is in flight (fm is L1/L2-hot)
        int mybad = 0;
        #pragma unroll
        for (int j = 0; j < 13; ++j) {
            int i = lane + j * 32;
            if (i < 392) {
                int p = i / HW, k = i - p * HW;
                float e = ((c_mb[p] >> k) & 1ULL) ? 1.0f : 0.0f;
                if (__ldg(fm + i) != e) mybad = 1;
            }
        }
        const bool fb = __any_sync(0xffffffffu, mybad);

        cp_wait_all();
        __syncwarp();                            // own slice visible warp-wide

        if (lane < rh) {
            const float* xr = wbuf + lane * HW;  // stride 49: conflict-free LDS
            float o[8];
            if (!fb) {
                const float x24 = xr[24];
                float R0 = xr[25] + xr[26] + xr[27];
                float R1 = xr[32] + xr[40] + xr[48];
                float R2 = xr[31] + xr[38] + xr[45];
                float R3 = xr[30] + xr[36] + xr[42];
                float R4 = xr[21] + xr[22] + xr[23];
                float R5 = xr[ 0] + xr[ 8] + xr[16];
                float R6 = xr[ 3] + xr[10] + xr[17];
                float R7 = xr[ 6] + xr[12] + xr[18];
                float I0 = xr[33] + xr[34] + xr[41];
                float I1 = xr[39] + xr[46] + xr[47];
                float I2 = xr[37] + xr[43] + xr[44];
                float I3 = xr[28] + xr[29] + xr[35];
                float I4 = xr[ 7] + xr[14] + xr[15];
                float I5 = xr[ 1] + xr[ 2] + xr[ 9];
                float I6 = xr[ 4] + xr[ 5] + xr[11];
                float I7 = xr[13] + xr[19] + xr[20];
                const float wgt = 0.1f;
                o[0] = (R0 + I0 + R1 + x24) * wgt;
                o[1] = (R1 + I1 + R2 + x24) * wgt;
                o[2] = (R2 + I2 + R3 + x24) * wgt;
                o[3] = (R3 + I3 + R4 + x24) * wgt;
                o[4] = (R4 + I4 + R5 + x24) * wgt;
                o[5] = (R5 + I5 + R6 + x24) * wgt;
                o[6] = (R6 + I6 + R7 + x24) * wgt;
                o[7] = (R7 + I7 + R0 + x24) * wgt;
            } else {
                // generic dense fallback (rare): read mask from gmem (cached)
                #pragma unroll
                for (int p = 0; p < 8; ++p) {
                    float acc = 0.0f, cnt = 0.0f;
                    for (int k = 0; k < HW; ++k) {
                        float m = __ldg(fm + p * HW + k);
                        acc += xr[k] * m;
                        cnt += (m != 0.0f) ? 1.0f : 0.0f;
                    }
                    o[p] = acc / cnt;
                }
            }
            float4* op = (float4*)(out + (wrow0 + lane) * 8);
            op[0] = make_float4(o[0], o[1], o[2], o[3]);
            op[1] = make_float4(o[4], o[5], o[6], o[7]);
        }
    } else {
        // ============ sal gather: one block per batch ============
        const int b = blk;
        const int M = 8 * N;
        const float4* sb4 = (const float4*)(s + (long long)b * SROW); // 16B aligned
        for (int i = t; i < SROW / 4; i += TPB) cp16(sbase + i * 16, sb4 + i);
        cp_commit();
        cp_wait_all();
        __syncthreads();

        float* ob = out + feat_elems + (long long)b * M;
        for (int q = t; q < M; q += TPB) {
            int n = q >> 3;
            int p = q & 7;
            ob[q] = sm[__ldg(sal_idx + p * N + n)];
        }
    }
}

extern "C" void kernel_launch(void* const* d_in, const int* in_sizes, int n_in,
                              void* d_out, int out_size) {
    const float* x       = (const float*)d_in[0];
    const float* s       = (const float*)d_in[1];
    const float* fm      = (const float*)d_in[2];
    const int*   sal_idx = (const int*)d_in[3];
    float*       out     = (float*)d_out;

    const int rows = in_sizes[0] / HW;    // B*C
    const int B    = in_sizes[1] / SROW;  // batch
    const int N    = in_sizes[3] / 8;     // points per direction
    const int nfb  = (rows + TPB - 1) / TPB;
    const long long feat_elems = (long long)rows * 8;

    fused_kernel<<<B + nfb, TPB>>>(x, s, fm, sal_idx, out, rows, B, N, feat_elems);
}

// round 6
// speedup vs baseline: 1.2562x; 1.1295x over previous
#include <cuda_runtime.h>
#include <cstdint>

// MultiDirectionPattern: masked 8-direction pooling + saliency gather.
// Feat path: warp-autonomous; each warp stages its 32 rows (6272B) with ONE
// cp.async.bulk (TMA path) completing on a per-warp mbarrier, verifies the
// sector mask against a constant bitmap while the copy flies, then computes
// the closed-form 10-cell/direction sums. No __syncthreads in the feat path.

static constexpr int HW    = 49;     // 7*7
static constexpr int TPB   = 128;
static constexpr int SROW  = 3136;   // 56*56
static constexpr int WROWS = 32;     // rows per warp
static constexpr int WF    = WROWS * HW;     // 1568 floats per warp slice
static constexpr int WBYTES = WF * 4;        // 6272 bytes
static constexpr int SM_FLOATS = 4 * WF;     // 6272 floats = 25088 B

// 392-bit bitmap of expected nonzero mask cells, packed so word j serves
// lanes of verify iteration j: bit (p*49+k) set <=> feat_mask[p][k] != 0.
__constant__ uint32_t c_bits[13] = {
    0x0F000000u, 0x00010307u, 0xC3830200u, 0x04000003u, 0x0000F1C3u,
    0x20C38F00u, 0x1E1C1810u, 0xE1E00000u, 0x00002060u, 0x41871E00u,
    0x20000000u, 0x00078E18u, 0x00000000u
};

__device__ __forceinline__ void cp16(uint32_t dst, const void* src) {
    asm volatile("cp.async.cg.shared.global [%0], [%1], 16;\n" :: "r"(dst), "l"(src));
}
__device__ __forceinline__ void cp4(uint32_t dst, const void* src) {
    asm volatile("cp.async.ca.shared.global [%0], [%1], 4;\n" :: "r"(dst), "l"(src));
}
__device__ __forceinline__ void cp_commit() {
    asm volatile("cp.async.commit_group;\n" ::: "memory");
}
__device__ __forceinline__ void cp_wait_all() {
    asm volatile("cp.async.wait_group 0;\n" ::: "memory");
}
__device__ __forceinline__ void mbar_init(uint32_t mbar, uint32_t cnt) {
    asm volatile("mbarrier.init.shared.b64 [%0], %1;\n" :: "r"(mbar), "r"(cnt) : "memory");
}
__device__ __forceinline__ void fence_async() {
    asm volatile("fence.proxy.async.shared::cta;\n" ::: "memory");
}
__device__ __forceinline__ void mbar_expect_tx(uint32_t mbar, uint32_t bytes) {
    asm volatile("mbarrier.arrive.expect_tx.shared.b64 _, [%0], %1;\n"
                 :: "r"(mbar), "r"(bytes) : "memory");
}
__device__ __forceinline__ void cp_bulk(uint32_t dst, const void* src,
                                        uint32_t bytes, uint32_t mbar) {
    asm volatile("cp.async.bulk.shared::cta.global.mbarrier::complete_tx::bytes "
                 "[%0], [%1], %2, [%3];\n"
                 :: "r"(dst), "l"(src), "r"(bytes), "r"(mbar) : "memory");
}
__device__ __forceinline__ void mbar_wait(uint32_t mbar, uint32_t parity) {
    uint32_t done;
    asm volatile(
        "{\n\t.reg .pred p;\n\t"
        "mbarrier.try_wait.parity.acquire.cta.shared::cta.b64 p, [%1], %2;\n\t"
        "selp.b32 %0, 1, 0, p;\n\t}"
        : "=r"(done) : "r"(mbar), "r"(parity) : "memory");
    if (!done) {
        asm volatile(
            "{\n\t.reg .pred P1;\n\t"
            "WL_%=:\n\t"
            "mbarrier.try_wait.parity.acquire.cta.shared::cta.b64 P1, [%0], %1, 0x989680;\n\t"
            "@P1 bra.uni WD_%=;\n\t"
            "bra.uni WL_%=;\n\t"
            "WD_%=:\n\t}"
            :: "r"(mbar), "r"(parity) : "memory");
    }
}

__global__ __launch_bounds__(TPB, 9) void fused_kernel(
    const float* __restrict__ x,
    const float* __restrict__ s,
    const float* __restrict__ fm,
    const int*   __restrict__ sal_idx,
    float*       __restrict__ out,
    int rows,             // B*C
    int B,                // batch (sal blocks are blk < B)
    int N,                // saliency points per direction
    long long feat_elems  // rows*8
) {
    __shared__ __align__(16) float sm[SM_FLOATS];
    __shared__ __align__(8) unsigned long long smbar[4];
    const int blk = blockIdx.x;
    const int t   = threadIdx.x;
    const uint32_t sbase = (uint32_t)__cvta_generic_to_shared(sm);
    const uint32_t mbase = (uint32_t)__cvta_generic_to_shared(smbar);

    if (blk >= B) {
        // ============ feat tile: warp-autonomous, 32 rows/warp ============
        const int w    = t >> 5;
        const int lane = t & 31;
        const long long wrow0 = (long long)(blk - B) * TPB + (long long)w * WROWS;
        long long rem = rows - wrow0;
        if (rem <= 0) return;                    // no barriers in this path
        const int rh = rem < WROWS ? (int)rem : WROWS;

        float* wbuf = sm + w * WF;
        const uint32_t dst  = sbase + (uint32_t)w * WBYTES;
        const uint32_t mbar = mbase + (uint32_t)w * 8;
        const float* xw = x + wrow0 * HW;        // wrow0 mult of 32 -> 16B aligned
        const bool full = (rh == WROWS);

        if (full) {
            if (lane == 0) {
                mbar_init(mbar, 1);
                fence_async();
                mbar_expect_tx(mbar, WBYTES);
                cp_bulk(dst, xw, WBYTES, mbar);
            }
            __syncwarp();
        } else {
            const int total = rh * HW;
            const int n4 = total >> 2;
            const float4* xw4 = (const float4*)xw;
            for (int i = lane; i < n4; i += 32) cp16(dst + i * 16, xw4 + i);
            for (int i = 4 * n4 + lane; i < total; i += 32) cp4(dst + i * 4, xw + i);
            cp_commit();
        }

        // verify mask while the copy is in flight (no div/mod: bitmap words)
        int mybad = 0;
        #pragma unroll
        for (int j = 0; j < 13; ++j) {
            int i = lane + j * 32;
            if (i < 392) {
                float e = ((c_bits[j] >> lane) & 1u) ? 1.0f : 0.0f;
                if (__ldg(fm + i) != e) mybad = 1;
            }
        }
        const bool fb = __any_sync(0xffffffffu, mybad);

        if (full) mbar_wait(mbar, 0);
        else      { cp_wait_all(); __syncwarp(); }

        if (lane < rh) {
            const float* xr = wbuf + lane * HW;  // stride 49: conflict-free LDS
            float o[8];
            if (!fb) {
                const float x24 = xr[24];
                float R0 = xr[25] + xr[26] + xr[27];
                float R1 = xr[32] + xr[40] + xr[48];
                float R2 = xr[31] + xr[38] + xr[45];
                float R3 = xr[30] + xr[36] + xr[42];
                float R4 = xr[21] + xr[22] + xr[23];
                float R5 = xr[ 0] + xr[ 8] + xr[16];
                float R6 = xr[ 3] + xr[10] + xr[17];
                float R7 = xr[ 6] + xr[12] + xr[18];
                float I0 = xr[33] + xr[34] + xr[41];
                float I1 = xr[39] + xr[46] + xr[47];
                float I2 = xr[37] + xr[43] + xr[44];
                float I3 = xr[28] + xr[29] + xr[35];
                float I4 = xr[ 7] + xr[14] + xr[15];
                float I5 = xr[ 1] + xr[ 2] + xr[ 9];
                float I6 = xr[ 4] + xr[ 5] + xr[11];
                float I7 = xr[13] + xr[19] + xr[20];
                const float wgt = 0.1f;
                o[0] = (R0 + I0 + R1 + x24) * wgt;
                o[1] = (R1 + I1 + R2 + x24) * wgt;
                o[2] = (R2 + I2 + R3 + x24) * wgt;
                o[3] = (R3 + I3 + R4 + x24) * wgt;
                o[4] = (R4 + I4 + R5 + x24) * wgt;
                o[5] = (R5 + I5 + R6 + x24) * wgt;
                o[6] = (R6 + I6 + R7 + x24) * wgt;
                o[7] = (R7 + I7 + R0 + x24) * wgt;
            } else {
                // generic dense fallback (rare): read mask from gmem (cached)
                #pragma unroll
                for (int p = 0; p < 8; ++p) {
                    float acc = 0.0f, cnt = 0.0f;
                    for (int k = 0; k < HW; ++k) {
                        float m = __ldg(fm + p * HW + k);
                        acc += xr[k] * m;
                        cnt += (m != 0.0f) ? 1.0f : 0.0f;
                    }
                    o[p] = acc / cnt;
                }
            }
            float4* op = (float4*)(out + (wrow0 + lane) * 8);
            op[0] = make_float4(o[0], o[1], o[2], o[3]);
            op[1] = make_float4(o[4], o[5], o[6], o[7]);
        }
    } else {
        // ============ sal gather: one block per batch ============
        const int b = blk;
        const int M = 8 * N;
        const float* sb = s + (long long)b * SROW;  // 12544B: 16B aligned
        const uint32_t mbar = mbase;
        if (t == 0) {
            mbar_init(mbar, 1);
            fence_async();
            mbar_expect_tx(mbar, SROW * 4);
            cp_bulk(sbase, sb, SROW * 4, mbar);
        }
        __syncthreads();
        mbar_wait(mbar, 0);

        float* ob = out + feat_elems + (long long)b * M;
        for (int q = t; q < M; q += TPB) {
            int n = q >> 3;
            int p = q & 7;
            ob[q] = sm[__ldg(sal_idx + p * N + n)];
        }
    }
}

extern "C" void kernel_launch(void* const* d_in, const int* in_sizes, int n_in,
                              void* d_out, int out_size) {
    const float* x       = (const float*)d_in[0];
    const float* s       = (const float*)d_in[1];
    const float* fm      = (const float*)d_in[2];
    const int*   sal_idx = (const int*)d_in[3];
    float*       out     = (float*)d_out;

    const int rows = in_sizes[0] / HW;    // B*C
    const int B    = in_sizes[1] / SROW;  // batch
    const int N    = in_sizes[3] / 8;     // points per direction
    const int nfb  = (rows + TPB - 1) / TPB;
    const long long feat_elems = (long long)rows * 8;

    fused_kernel<<<B + nfb, TPB>>>(x, s, fm, sal_idx, out, rows, B, N, feat_elems);
}

// round 7
// speedup vs baseline: 1.2684x; 1.0097x over previous
#include <cuda_runtime.h>
#include <cstdint>

// MultiDirectionPattern: masked 8-direction pooling + saliency gather.
// 64-thread CTAs (2 warps, 12.5KB smem -> 16 CTAs/SM). Feat path is
// warp-autonomous: each warp stages its 32 rows (6272B) with ONE
// cp.async.bulk completing on a per-warp mbarrier, verifies the sector mask
// against a constant bitmap while the copy flies, then computes the
// closed-form 10-cell/direction sums. No __syncthreads in the feat path.

static constexpr int HW    = 49;     // 7*7
static constexpr int TPB   = 64;
static constexpr int SROW  = 3136;   // 56*56
static constexpr int WROWS = 32;     // rows per warp
static constexpr int WF    = WROWS * HW;     // 1568 floats per warp slice
static constexpr int WBYTES = WF * 4;        // 6272 bytes
static constexpr int SM_FLOATS = 2 * WF;     // 3136 floats = 12544 B (== SROW*4)

// 392-bit bitmap of expected nonzero mask cells, word j serves verify
// iteration j: bit (p*49+k) of the stream set <=> feat_mask[p][k] != 0.
__constant__ uint32_t c_bits[13] = {
    0x0F000000u, 0x00010307u, 0xC3830200u, 0x04000003u, 0x0000F1C3u,
    0x20C38F00u, 0x1E1C1810u, 0xE1E00000u, 0x00002060u, 0x41871E00u,
    0x20000000u, 0x00078E18u, 0x00000000u
};

__device__ __forceinline__ void cp16(uint32_t dst, const void* src) {
    asm volatile("cp.async.cg.shared.global [%0], [%1], 16;\n" :: "r"(dst), "l"(src));
}
__device__ __forceinline__ void cp4(uint32_t dst, const void* src) {
    asm volatile("cp.async.ca.shared.global [%0], [%1], 4;\n" :: "r"(dst), "l"(src));
}
__device__ __forceinline__ void cp_commit() {
    asm volatile("cp.async.commit_group;\n" ::: "memory");
}
__device__ __forceinline__ void cp_wait_all() {
    asm volatile("cp.async.wait_group 0;\n" ::: "memory");
}
__device__ __forceinline__ void mbar_init(uint32_t mbar, uint32_t cnt) {
    asm volatile("mbarrier.init.shared.b64 [%0], %1;\n" :: "r"(mbar), "r"(cnt) : "memory");
}
__device__ __forceinline__ void fence_async() {
    asm volatile("fence.proxy.async.shared::cta;\n" ::: "memory");
}
__device__ __forceinline__ void mbar_expect_tx(uint32_t mbar, uint32_t bytes) {
    asm volatile("mbarrier.arrive.expect_tx.shared.b64 _, [%0], %1;\n"
                 :: "r"(mbar), "r"(bytes) : "memory");
}
__device__ __forceinline__ void cp_bulk(uint32_t dst, const void* src,
                                        uint32_t bytes, uint32_t mbar) {
    asm volatile("cp.async.bulk.shared::cta.global.mbarrier::complete_tx::bytes "
                 "[%0], [%1], %2, [%3];\n"
                 :: "r"(dst), "l"(src), "r"(bytes), "r"(mbar) : "memory");
}
__device__ __forceinline__ void mbar_wait(uint32_t mbar, uint32_t parity) {
    uint32_t done;
    asm volatile(
        "{\n\t.reg .pred p;\n\t"
        "mbarrier.try_wait.parity.acquire.cta.shared::cta.b64 p, [%1], %2;\n\t"
        "selp.b32 %0, 1, 0, p;\n\t}"
        : "=r"(done) : "r"(mbar), "r"(parity) : "memory");
    if (!done) {
        asm volatile(
            "{\n\t.reg .pred P1;\n\t"
            "WL_%=:\n\t"
            "mbarrier.try_wait.parity.acquire.cta.shared::cta.b64 P1, [%0], %1, 0x989680;\n\t"
            "@P1 bra.uni WD_%=;\n\t"
            "bra.uni WL_%=;\n\t"
            "WD_%=:\n\t}"
            :: "r"(mbar), "r"(parity) : "memory");
    }
}

__global__ __launch_bounds__(TPB, 16) void fused_kernel(
    const float* __restrict__ x,
    const float* __restrict__ s,
    const float* __restrict__ fm,
    const int*   __restrict__ sal_idx,
    float*       __restrict__ out,
    int rows,             // B*C
    int B,                // batch (sal blocks are blk < B)
    int N,                // saliency points per direction
    long long feat_elems  // rows*8
) {
    __shared__ __align__(16) float sm[SM_FLOATS];
    __shared__ __align__(8) unsigned long long smbar[2];
    const int blk = blockIdx.x;
    const int t   = threadIdx.x;
    const uint32_t sbase = (uint32_t)__cvta_generic_to_shared(sm);
    const uint32_t mbase = (uint32_t)__cvta_generic_to_shared(smbar);

    if (blk >= B) {
        // ============ feat tile: warp-autonomous, 32 rows/warp ============
        const int w    = t >> 5;
        const int lane = t & 31;
        const long long wrow0 = (long long)(blk - B) * TPB + (long long)w * WROWS;
        long long rem = rows - wrow0;
        if (rem <= 0) return;                    // no barriers in this path
        const int rh = rem < WROWS ? (int)rem : WROWS;

        float* wbuf = sm + w * WF;
        const uint32_t dst  = sbase + (uint32_t)w * WBYTES;
        const uint32_t mbar = mbase + (uint32_t)w * 8;
        const float* xw = x + wrow0 * HW;        // wrow0 mult of 32 -> 16B aligned
        const bool full = (rh == WROWS);

        if (full) {
            if (lane == 0) {
                mbar_init(mbar, 1);
                fence_async();
                mbar_expect_tx(mbar, WBYTES);
                cp_bulk(dst, xw, WBYTES, mbar);
            }
            __syncwarp();
        } else {
            const int total = rh * HW;
            const int n4 = total >> 2;
            const float4* xw4 = (const float4*)xw;
            for (int i = lane; i < n4; i += 32) cp16(dst + i * 16, xw4 + i);
            for (int i = 4 * n4 + lane; i < total; i += 32) cp4(dst + i * 4, xw + i);
            cp_commit();
        }

        // verify mask while the copy is in flight (bitmap words, no div/mod)
        int mybad = 0;
        #pragma unroll
        for (int j = 0; j < 13; ++j) {
            int i = lane + j * 32;
            if (i < 392) {
                float e = ((c_bits[j] >> lane) & 1u) ? 1.0f : 0.0f;
                if (__ldg(fm + i) != e) mybad = 1;
            }
        }
        const bool fb = __any_sync(0xffffffffu, mybad);

        if (full) mbar_wait(mbar, 0);
        else      { cp_wait_all(); __syncwarp(); }

        if (lane < rh) {
            const float* xr = wbuf + lane * HW;  // stride 49: conflict-free LDS
            float o[8];
            if (!fb) {
                const float x24 = xr[24];
                float R0 = xr[25] + xr[26] + xr[27];
                float R1 = xr[32] + xr[40] + xr[48];
                float R2 = xr[31] + xr[38] + xr[45];
                float R3 = xr[30] + xr[36] + xr[42];
                float R4 = xr[21] + xr[22] + xr[23];
                float R5 = xr[ 0] + xr[ 8] + xr[16];
                float R6 = xr[ 3] + xr[10] + xr[17];
                float R7 = xr[ 6] + xr[12] + xr[18];
                float I0 = xr[33] + xr[34] + xr[41];
                float I1 = xr[39] + xr[46] + xr[47];
                float I2 = xr[37] + xr[43] + xr[44];
                float I3 = xr[28] + xr[29] + xr[35];
                float I4 = xr[ 7] + xr[14] + xr[15];
                float I5 = xr[ 1] + xr[ 2] + xr[ 9];
                float I6 = xr[ 4] + xr[ 5] + xr[11];
                float I7 = xr[13] + xr[19] + xr[20];
                const float wgt = 0.1f;
                o[0] = (R0 + I0 + R1 + x24) * wgt;
                o[1] = (R1 + I1 + R2 + x24) * wgt;
                o[2] = (R2 + I2 + R3 + x24) * wgt;
                o[3] = (R3 + I3 + R4 + x24) * wgt;
                o[4] = (R4 + I4 + R5 + x24) * wgt;
                o[5] = (R5 + I5 + R6 + x24) * wgt;
                o[6] = (R6 + I6 + R7 + x24) * wgt;
                o[7] = (R7 + I7 + R0 + x24) * wgt;
            } else {
                // generic dense fallback (rare): read mask from gmem (cached)
                #pragma unroll
                for (int p = 0; p < 8; ++p) {
                    float acc = 0.0f, cnt = 0.0f;
                    for (int k = 0; k < HW; ++k) {
                        float m = __ldg(fm + p * HW + k);
                        acc += xr[k] * m;
                        cnt += (m != 0.0f) ? 1.0f : 0.0f;
                    }
                    o[p] = acc / cnt;
                }
            }
            float4* op = (float4*)(out + (wrow0 + lane) * 8);
            op[0] = make_float4(o[0], o[1], o[2], o[3]);
            op[1] = make_float4(o[4], o[5], o[6], o[7]);
        }
    } else {
        // ============ sal gather: one block per batch ============
        const int b = blk;
        const float* sb = s + (long long)b * SROW;  // 12544B: 16B aligned
        const uint32_t mbar = mbase;
        if (t == 0) {
            mbar_init(mbar, 1);
            fence_async();
            mbar_expect_tx(mbar, SROW * 4);
            cp_bulk(sbase, sb, SROW * 4, mbar);
        }
        __syncthreads();
        mbar_wait(mbar, 0);

        // one thread per output point n: 8 gathers + 2 STG.128
        float* ob = out + feat_elems + (long long)b * (8LL * N);
        for (int n = t; n < N; n += TPB) {
            float v[8];
            #pragma unroll
            for (int p = 0; p < 8; ++p)
                v[p] = sm[__ldg(sal_idx + p * N + n)];
            float4* op = (float4*)(ob + n * 8);
            op[0] = make_float4(v[0], v[1], v[2], v[3]);
            op[1] = make_float4(v[4], v[5], v[6], v[7]);
        }
    }
}

extern "C" void kernel_launch(void* const* d_in, const int* in_sizes, int n_in,
                              void* d_out, int out_size) {
    const float* x       = (const float*)d_in[0];
    const float* s       = (const float*)d_in[1];
    const float* fm      = (const float*)d_in[2];
    const int*   sal_idx = (const int*)d_in[3];
    float*       out     = (float*)d_out;

    const int rows = in_sizes[0] / HW;    // B*C
    const int B    = in_sizes[1] / SROW;  // batch
    const int N    = in_sizes[3] / 8;     // points per direction
    const int nfb  = (rows + TPB - 1) / TPB;
    const long long feat_elems = (long long)rows * 8;

    fused_kernel<<<B + nfb, TPB>>>(x, s, fm, sal_idx, out, rows, B, N, feat_elems);
}